// round 5
// baseline (speedup 1.0000x reference)
#include <cuda_runtime.h>
#include <cstdint>

// out = X * W[idx][0] + Y * W[idx][1], idx = reward[b,s] in {0,1}
// X,Y: (4,4096,2048) fp32; reward: (4,4096,1) int32; W: (2,2) fp32.
// HBM-bound blend. Each block owns 1024 contiguous float4 = exactly 2 rows.
// 4 float4/thread at stride 256 -> every LDG/STG is a fully coalesced
// 512B warp wavefront; 8 front-batched loads/thread for MLP.

__global__ __launch_bounds__(256)
void blend_kernel4(const float4* __restrict__ X,
                   const float4* __restrict__ Y,
                   const int* __restrict__ reward,
                   const float* __restrict__ W,
                   float4* __restrict__ out)
{
    int base = blockIdx.x * 1024 + threadIdx.x;   // block covers [b*1024, b*1024+1024)

    int row0 = blockIdx.x * 2;                    // k=0,1 -> row0 ; k=2,3 -> row0+1
    int idx0 = (reward[row0]     != 0) ? 1 : 0;
    int idx1 = (reward[row0 + 1] != 0) ? 1 : 0;

    float a0 = W[2 * idx0], b0 = W[2 * idx0 + 1];
    float a1 = W[2 * idx1], b1 = W[2 * idx1 + 1];

    // Front-batch all 8 global loads.
    float4 x0 = X[base];
    float4 x1 = X[base + 256];
    float4 x2 = X[base + 512];
    float4 x3 = X[base + 768];
    float4 y0 = Y[base];
    float4 y1 = Y[base + 256];
    float4 y2 = Y[base + 512];
    float4 y3 = Y[base + 768];

    float4 o0, o1, o2, o3;
    o0.x = fmaf(x0.x, a0, y0.x * b0);
    o0.y = fmaf(x0.y, a0, y0.y * b0);
    o0.z = fmaf(x0.z, a0, y0.z * b0);
    o0.w = fmaf(x0.w, a0, y0.w * b0);
    o1.x = fmaf(x1.x, a0, y1.x * b0);
    o1.y = fmaf(x1.y, a0, y1.y * b0);
    o1.z = fmaf(x1.z, a0, y1.z * b0);
    o1.w = fmaf(x1.w, a0, y1.w * b0);
    o2.x = fmaf(x2.x, a1, y2.x * b1);
    o2.y = fmaf(x2.y, a1, y2.y * b1);
    o2.z = fmaf(x2.z, a1, y2.z * b1);
    o2.w = fmaf(x2.w, a1, y2.w * b1);
    o3.x = fmaf(x3.x, a1, y3.x * b1);
    o3.y = fmaf(x3.y, a1, y3.y * b1);
    o3.z = fmaf(x3.z, a1, y3.z * b1);
    o3.w = fmaf(x3.w, a1, y3.w * b1);

    out[base]       = o0;
    out[base + 256] = o1;
    out[base + 512] = o2;
    out[base + 768] = o3;
}

extern "C" void kernel_launch(void* const* d_in, const int* in_sizes, int n_in,
                              void* d_out, int out_size)
{
    const float4* X      = (const float4*)d_in[0];
    const float4* Y      = (const float4*)d_in[1];
    const int*    reward = (const int*)d_in[2];
    const float*  W      = (const float*)d_in[3];
    float4*       out    = (float4*)d_out;

    int n  = out_size;          // 4*4096*2048 = 33554432 fp32
    int n4 = n / 4;             // 8388608 float4
    int blocks = n4 / 1024;     // 8192 blocks, exact (2 rows per block)

    blend_kernel4<<<blocks, 256>>>(X, Y, reward, W, out);
}

// round 6
// speedup vs baseline: 1.0221x; 1.0221x over previous
#include <cuda_runtime.h>
#include <cstdint>

// out = X * W[idx][0] + Y * W[idx][1], idx = reward[b,s] in {0,1}
// X,Y: (4,4096,2048) fp32; reward: (4,4096,1) int32; W: (2,2) fp32.
// HBM-bound blend. One block = one (b,s) row = 512 contiguous float4.
// 2 float4/thread at stride 256: fully coalesced 512B wavefronts, MLP=4
// front-batched loads/thread (R4's sweet spot), single uniform reward load.

__global__ __launch_bounds__(256)
void blend_kernel_row(const float4* __restrict__ X,
                      const float4* __restrict__ Y,
                      const int* __restrict__ reward,
                      const float* __restrict__ W,
                      float4* __restrict__ out)
{
    int base = blockIdx.x * 512 + threadIdx.x;   // row = blockIdx.x

    int idx = (reward[blockIdx.x] != 0) ? 1 : 0; // uniform across block
    float a = W[2 * idx];
    float b = W[2 * idx + 1];

    // Front-batch 4 global loads (MLP=4, R4's sweet spot).
    float4 x0 = X[base];
    float4 x1 = X[base + 256];
    float4 y0 = Y[base];
    float4 y1 = Y[base + 256];

    float4 o0, o1;
    o0.x = fmaf(x0.x, a, y0.x * b);
    o0.y = fmaf(x0.y, a, y0.y * b);
    o0.z = fmaf(x0.z, a, y0.z * b);
    o0.w = fmaf(x0.w, a, y0.w * b);
    o1.x = fmaf(x1.x, a, y1.x * b);
    o1.y = fmaf(x1.y, a, y1.y * b);
    o1.z = fmaf(x1.z, a, y1.z * b);
    o1.w = fmaf(x1.w, a, y1.w * b);

    out[base]       = o0;
    out[base + 256] = o1;
}

extern "C" void kernel_launch(void* const* d_in, const int* in_sizes, int n_in,
                              void* d_out, int out_size)
{
    const float4* X      = (const float4*)d_in[0];
    const float4* Y      = (const float4*)d_in[1];
    const int*    reward = (const int*)d_in[2];
    const float*  W      = (const float*)d_in[3];
    float4*       out    = (float4*)d_out;

    int n  = out_size;          // 4*4096*2048 = 33554432 fp32
    int n4 = n / 4;             // 8388608 float4
    int blocks = n4 / 512;      // 16384 blocks, one row each (exact)

    blend_kernel_row<<<blocks, 256>>>(X, Y, reward, W, out);
}

// round 7
// speedup vs baseline: 1.0263x; 1.0041x over previous
#include <cuda_runtime.h>
#include <cstdint>

// out = X * W[idx][0] + Y * W[idx][1], idx = reward[b,s] in {0,1}
// X,Y: (4,4096,2048) fp32; reward: (4,4096,1) int32; W: (2,2) fp32.
// HBM-bound blend. One block = one (b,s) row = 512 contiguous float4.
// 2 float4/thread at stride 256 (fully coalesced 512B wavefronts, MLP=4).
// Streaming cache hints (__ldcs/__stcs): zero-reuse data, evict-first in L2.

__global__ __launch_bounds__(256)
void blend_kernel_rows(const float4* __restrict__ X,
                       const float4* __restrict__ Y,
                       const int* __restrict__ reward,
                       const float* __restrict__ W,
                       float4* __restrict__ out)
{
    int base = blockIdx.x * 512 + threadIdx.x;   // row = blockIdx.x

    int idx = (reward[blockIdx.x] != 0) ? 1 : 0; // uniform across block
    float a = W[2 * idx];
    float b = W[2 * idx + 1];

    // Front-batch 4 global loads (MLP=4), streaming policy.
    float4 x0 = __ldcs(&X[base]);
    float4 x1 = __ldcs(&X[base + 256]);
    float4 y0 = __ldcs(&Y[base]);
    float4 y1 = __ldcs(&Y[base + 256]);

    float4 o0, o1;
    o0.x = fmaf(x0.x, a, y0.x * b);
    o0.y = fmaf(x0.y, a, y0.y * b);
    o0.z = fmaf(x0.z, a, y0.z * b);
    o0.w = fmaf(x0.w, a, y0.w * b);
    o1.x = fmaf(x1.x, a, y1.x * b);
    o1.y = fmaf(x1.y, a, y1.y * b);
    o1.z = fmaf(x1.z, a, y1.z * b);
    o1.w = fmaf(x1.w, a, y1.w * b);

    __stcs(&out[base],       o0);
    __stcs(&out[base + 256], o1);
}

extern "C" void kernel_launch(void* const* d_in, const int* in_sizes, int n_in,
                              void* d_out, int out_size)
{
    const float4* X      = (const float4*)d_in[0];
    const float4* Y      = (const float4*)d_in[1];
    const int*    reward = (const int*)d_in[2];
    const float*  W      = (const float*)d_in[3];
    float4*       out    = (float4*)d_out;

    int n  = out_size;          // 4*4096*2048 = 33554432 fp32
    int n4 = n / 4;             // 8388608 float4
    int blocks = n4 / 512;      // 16384 blocks, one row each (exact)

    blend_kernel_rows<<<blocks, 256>>>(X, Y, reward, W, out);
}